// round 6
// baseline (speedup 1.0000x reference)
#include <cuda_runtime.h>
#include <cuda_bf16.h>
#include <math.h>

#define BB      8
#define TT      512
#define DIMIN   768
#define WIDTH   8192
#define NHEADS  8
#define NEMBDS  128
#define DH_QK   16
#define DH_V    1024
#define MM      (BB * TT)          /* 4096 */
#define LAM     (1.0f / 3072.0f)
#define EPSV    1e-6f
#define KT      64                 /* K-tile elems (128B bf16 rows) */

// ---------------- fp32 scratch ----------------------------------------------
__device__ float g_x     [MM * DIMIN];
__device__ float g_q     [MM * NEMBDS];
__device__ float g_k     [MM * NEMBDS];
__device__ float g_scores[(long)BB * NHEADS * TT * TT];
__device__ float g_Dz    [MM * DIMIN];
__device__ float g_zpred [MM * WIDTH];
__device__ float g_znov  [MM * WIDTH];
__device__ float g_proj  [MM];
__device__ float g_part  [2 * MM * DIMIN];           /* >= 8*MM*NEMBDS */

// ---------------- bf16 hi/lo split buffers ([0]=hi, [1]=lo) ------------------
__device__ __align__(256) __nv_bfloat16 s_x    [2][MM * DIMIN];
__device__ __align__(256) __nv_bfloat16 s_x2   [2][MM * DIMIN];
__device__ __align__(256) __nv_bfloat16 s_D    [2][WIDTH * DIMIN];
__device__ __align__(256) __nv_bfloat16 s_DT   [2][DIMIN * WIDTH];
__device__ __align__(256) __nv_bfloat16 s_Wk   [2][NEMBDS * WIDTH];
__device__ __align__(256) __nv_bfloat16 s_Wq   [2][NEMBDS * WIDTH];
__device__ __align__(256) __nv_bfloat16 s_Wv   [2][WIDTH * WIDTH];
__device__ __align__(256) __nv_bfloat16 s_Wo   [2][WIDTH * WIDTH];
__device__ __align__(256) __nv_bfloat16 s_zin  [2][MM * WIDTH];
__device__ __align__(256) __nv_bfloat16 s_v    [2][MM * WIDTH];
__device__ __align__(256) __nv_bfloat16 s_vT   [2][MM * WIDTH];
__device__ __align__(256) __nv_bfloat16 s_pr   [2][(long)BB * NHEADS * TT * TT];
__device__ __align__(256) __nv_bfloat16 s_at   [2][MM * WIDTH];
__device__ __align__(256) __nv_bfloat16 s_zp   [2][MM * WIDTH];
__device__ __align__(256) __nv_bfloat16 s_zs   [2][MM * WIDTH];

// ---------------- helpers ----------------------------------------------------
__device__ __forceinline__ unsigned smem_u32(const void* p) {
    unsigned a;
    asm("{ .reg .u64 t; cvta.to.shared.u64 t, %1; cvt.u32.u64 %0, t; }"
        : "=r"(a) : "l"(p));
    return a;
}
__device__ __forceinline__ unsigned swz(unsigned off) {
    return off ^ ((off >> 3) & 0x70);
}
__device__ __forceinline__ void cpa(unsigned dst, const void* src, int sz) {
    asm volatile("cp.async.cg.shared.global [%0], [%1], 16, %2;"
                 :: "r"(dst), "l"(src), "r"(sz) : "memory");
}
#define CPA_COMMIT() asm volatile("cp.async.commit_group;" ::: "memory")
#define CPA_WAIT1()  asm volatile("cp.async.wait_group 1;" ::: "memory")
#define CPA_WAIT0()  asm volatile("cp.async.wait_group 0;" ::: "memory")

#define LDSM4(r, a)                                                             \
    asm volatile("ldmatrix.sync.aligned.m8n8.x4.shared.b16 {%0,%1,%2,%3},[%4];" \
                 : "=r"((r)[0]), "=r"((r)[1]), "=r"((r)[2]), "=r"((r)[3])       \
                 : "r"(a))
#define LDSM2(r, a)                                                             \
    asm volatile("ldmatrix.sync.aligned.m8n8.x2.shared.b16 {%0,%1},[%2];"       \
                 : "=r"((r)[0]), "=r"((r)[1]) : "r"(a))
#define MMA(d, a, b)                                                            \
    asm volatile("mma.sync.aligned.m16n8k16.row.col.f32.bf16.bf16.f32 "         \
                 "{%0,%1,%2,%3},{%4,%5,%6,%7},{%8,%9},{%0,%1,%2,%3};"           \
                 : "+f"((d)[0]), "+f"((d)[1]), "+f"((d)[2]), "+f"((d)[3])       \
                 : "r"((a)[0]), "r"((a)[1]), "r"((a)[2]), "r"((a)[3]),          \
                   "r"((b)[0]), "r"((b)[1]))

__device__ __forceinline__ void split1(float v, __nv_bfloat16& h, __nv_bfloat16& l) {
    h = __float2bfloat16(v);
    l = __float2bfloat16(v - __bfloat162float(h));
}

// ---------------- GEMM: pre-split bf16 operands, cp.async pipeline -----------
// C = act(alpha * A @ B^T + bias), A (M x K) hi/lo, B (N x K) hi/lo, row-major.
// NTILE in {128, 256}.  EPI: 0 = fp32, 1 = split, 2 = both.
template<int NTILE, bool RELU, bool BIAS, bool SHIFT, int EPI>
__global__ void __launch_bounds__(256, 1) tgemm(
    const __nv_bfloat16* __restrict__ Ah, const __nv_bfloat16* __restrict__ Al, int lda,
    const __nv_bfloat16* __restrict__ Bh, const __nv_bfloat16* __restrict__ Bl, int ldb,
    float* __restrict__ Cf, __nv_bfloat16* __restrict__ Ch, __nv_bfloat16* __restrict__ Cl,
    int ldc, int K, float alpha, const float* __restrict__ bias,
    long sA, long sB, int zdiv, long sCo, long sCi)
{
    constexpr int NST  = (NTILE == 256) ? 2 : 3;       // pipeline stages
    constexpr int BBYT = NTILE * 128;                  // B hi bytes per stage
    constexpr int STBY = 32768 + 2 * BBYT;             // stage bytes
    constexpr int NWT  = (NTILE == 256) ? 8 : 4;       // n-frags per warp

    extern __shared__ char sm[];
    const unsigned sb = smem_u32(sm);
    const int tid = threadIdx.x, wid = tid >> 5, lane = tid & 31;

    const int z = blockIdx.z;
    Ah += (long)z * sA;  Al += (long)z * sA;
    Bh += (long)z * sB;  Bl += (long)z * sB;
    const long coff = (long)(z / zdiv) * sCo + (long)(z % zdiv) * sCi;

    // L2-aware rasterization: supertile of G n-blocks, sweep m within it
    int lin = blockIdx.y * gridDim.x + blockIdx.x;
    int G = (gridDim.x >= 8) ? 8 : gridDim.x;
    int span = G * gridDim.y;
    int bxn = (lin / span) * G + (lin % span) % G;
    int bym = (lin % span) / G;

    const int m0 = bym * 128;
    const int n0 = bxn * NTILE;
    const int mw = (wid & 1) * 64;
    const int nw = (wid >> 1) * (NWT * 8);

    float acc[4][NWT][4];
#pragma unroll
    for (int i = 0; i < 4; i++)
#pragma unroll
        for (int j = 0; j < NWT; j++)
#pragma unroll
            for (int l = 0; l < 4; l++) acc[i][j][l] = 0.f;

    const int nkt = K / KT;

    auto issue = [&](int kt) {
        const unsigned st = sb + (kt % NST) * STBY;
#pragma unroll
        for (int i = 0; i < 4; i++) {
            int idx = i * 256 + tid;            // 0..1023
            int row = idx >> 3, c = idx & 7;
            unsigned d = st + swz(row * 128 + c * 16);
            long off; int sz = 16;
            if (SHIFT) {
                int gr = m0 + row;
                int ok = (gr & (TT - 1)) != 0;
                off = (long)(ok ? gr - 1 : 0) * lda + kt * KT + c * 8;
                sz = ok ? 16 : 0;
            } else {
                off = (long)(m0 + row) * lda + kt * KT + c * 8;
            }
            cpa(d,         Ah + off, sz);
            cpa(d + 16384, Al + off, sz);
        }
#pragma unroll
        for (int i = 0; i < NTILE / 32; i++) {
            int idx = i * 256 + tid;
            int row = idx >> 3, c = idx & 7;
            unsigned d = st + 32768 + swz(row * 128 + c * 16);
            long off = (long)(n0 + row) * ldb + kt * KT + c * 8;
            cpa(d,        Bh + off, 16);
            cpa(d + BBYT, Bl + off, 16);
        }
        CPA_COMMIT();
    };

    issue(0);
    issue(1);

    const int arow = lane & 15, ach = lane >> 4;
    const int brow = lane & 7,  bch = (lane >> 3) & 1;

    for (int kt = 0; kt < nkt; kt++) {
        if (kt == nkt - 1) { CPA_WAIT0(); } else { CPA_WAIT1(); }
        __syncthreads();

        const unsigned st  = sb + (kt % NST) * STBY;
        const unsigned ahb = st, alb = st + 16384, bhb = st + 32768, blb = st + 32768 + BBYT;
#pragma unroll
        for (int ks = 0; ks < 4; ks++) {
            unsigned ah[4][4], al[4][4];
#pragma unroll
            for (int mt = 0; mt < 4; mt++) {
                unsigned o = swz((mw + mt * 16 + arow) * 128 + ks * 32 + 16 * ach);
                LDSM4(ah[mt], ahb + o);
                LDSM4(al[mt], alb + o);
            }
#pragma unroll
            for (int nt = 0; nt < NWT; nt++) {
                unsigned o = swz((nw + nt * 8 + brow) * 128 + ks * 32 + 16 * bch);
                unsigned bh[2], bl[2];
                LDSM2(bh, bhb + o);
                LDSM2(bl, blb + o);
#pragma unroll
                for (int mt = 0; mt < 4; mt++) {
                    MMA(acc[mt][nt], ah[mt], bh);
                    MMA(acc[mt][nt], ah[mt], bl);
                    MMA(acc[mt][nt], al[mt], bh);
                }
            }
        }
        __syncthreads();
        if (kt + 2 < nkt) issue(kt + 2);
    }

    // ---- epilogue ----
#pragma unroll
    for (int mt = 0; mt < 4; mt++) {
        int r0 = m0 + mw + mt * 16 + (lane >> 2);
#pragma unroll
        for (int nt = 0; nt < NWT; nt++) {
            int c = n0 + nw + nt * 8 + (lane & 3) * 2;
            float b0 = BIAS ? bias[c] : 0.f;
            float b1 = BIAS ? bias[c + 1] : 0.f;
#pragma unroll
            for (int half = 0; half < 2; half++) {
                int r = r0 + half * 8;
                float v0 = alpha * acc[mt][nt][half * 2 + 0] + b0;
                float v1 = alpha * acc[mt][nt][half * 2 + 1] + b1;
                if (RELU) { v0 = fmaxf(v0, 0.f); v1 = fmaxf(v1, 0.f); }
                long e = coff + (long)r * ldc + c;
                if (EPI == 0 || EPI == 2)
                    *(float2*)(Cf + e) = make_float2(v0, v1);
                if (EPI == 1 || EPI == 2) {
                    __nv_bfloat162 h = __floats2bfloat162_rn(v0, v1);
                    float r0f = v0 - __bfloat162float(h.x);
                    float r1f = v1 - __bfloat162float(h.y);
                    __nv_bfloat162 l = __floats2bfloat162_rn(r0f, r1f);
                    *(__nv_bfloat162*)(Ch + e) = h;
                    *(__nv_bfloat162*)(Cl + e) = l;
                }
            }
        }
    }
}

// ---------------- split / transpose kernels ----------------------------------
__global__ void wsplit_kernel(const float* __restrict__ in,
                              __nv_bfloat16* __restrict__ hi,
                              __nv_bfloat16* __restrict__ lo, long n4) {
    long i = (long)blockIdx.x * blockDim.x + threadIdx.x;
    if (i >= n4) return;
    float4 v = ((const float4*)in)[i];
    __nv_bfloat162 h01 = __floats2bfloat162_rn(v.x, v.y);
    __nv_bfloat162 h23 = __floats2bfloat162_rn(v.z, v.w);
    __nv_bfloat162 l01 = __floats2bfloat162_rn(v.x - __bfloat162float(h01.x),
                                               v.y - __bfloat162float(h01.y));
    __nv_bfloat162 l23 = __floats2bfloat162_rn(v.z - __bfloat162float(h23.x),
                                               v.w - __bfloat162float(h23.y));
    ((uint2*)hi)[i] = make_uint2(*(unsigned*)&h01, *(unsigned*)&h23);
    ((uint2*)lo)[i] = make_uint2(*(unsigned*)&l01, *(unsigned*)&l23);
}

__global__ void prep_kernel(const float* __restrict__ xin,
                            const float* __restrict__ bvec) {
    long i = (long)blockIdx.x * blockDim.x + threadIdx.x;
    if (i >= MM * (DIMIN / 4)) return;
    int c4 = (int)(i % (DIMIN / 4));
    float4 xv = ((const float4*)xin)[i];
    float4 bv = ((const float4*)bvec)[c4];
    float4 r = make_float4(xv.x - bv.x, xv.y - bv.y, xv.z - bv.z, xv.w - bv.w);
    ((float4*)g_x)[i] = r;
    __nv_bfloat162 h01 = __floats2bfloat162_rn(r.x, r.y);
    __nv_bfloat162 h23 = __floats2bfloat162_rn(r.z, r.w);
    __nv_bfloat162 l01 = __floats2bfloat162_rn(r.x - __bfloat162float(h01.x),
                                               r.y - __bfloat162float(h01.y));
    __nv_bfloat162 l23 = __floats2bfloat162_rn(r.z - __bfloat162float(h23.x),
                                               r.w - __bfloat162float(h23.y));
    ((uint2*)&s_x[0][0])[i] = make_uint2(*(unsigned*)&h01, *(unsigned*)&h23);
    ((uint2*)&s_x[1][0])[i] = make_uint2(*(unsigned*)&l01, *(unsigned*)&l23);
}

// DT[n][k] = D[k][n], split  (D: WIDTH x DIMIN)
__global__ void dtsplit_kernel(const float* __restrict__ D) {
    __shared__ float tl[32][33];
    int n0 = blockIdx.x * 32, k0 = blockIdx.y * 32;
    int tx = threadIdx.x, ty = threadIdx.y;     // (32, 8)
#pragma unroll
    for (int j = 0; j < 4; j++)
        tl[ty + j * 8][tx] = D[(long)(k0 + ty + j * 8) * DIMIN + n0 + tx];
    __syncthreads();
#pragma unroll
    for (int j = 0; j < 4; j++) {
        int nr = ty + j * 8;
        float v = tl[tx][nr];
        __nv_bfloat16 h, l; split1(v, h, l);
        long o = (long)(n0 + nr) * WIDTH + k0 + tx;
        s_DT[0][o] = h; s_DT[1][o] = l;
    }
}

// vT[(b*8+h)*1024+d][t] = v[b*512+t][h*1024+d]
__global__ void vtrans_kernel() {
    __shared__ __nv_bfloat16 tl[2][32][33];
    int b = blockIdx.z;
    int d0 = blockIdx.x * 32;
    int t0 = blockIdx.y * 32;
    int tx = threadIdx.x, ty = threadIdx.y;   // (32, 8)
#pragma unroll
    for (int j = 0; j < 4; j++) {
        int r = ty + j * 8;
        long src = (long)(b * TT + t0 + r) * WIDTH + d0 + tx;
        tl[0][r][tx] = s_v[0][src];
        tl[1][r][tx] = s_v[1][src];
    }
    __syncthreads();
    int h = d0 >> 10, dbase = d0 & 1023;
#pragma unroll
    for (int j = 0; j < 4; j++) {
        int dr = ty + j * 8;
        long orow = (long)(b * NHEADS + h) * DH_V + dbase + dr;
        long dst = orow * TT + t0 + tx;
        s_vT[0][dst] = tl[0][tx][dr];
        s_vT[1][dst] = tl[1][tx][dr];
    }
}

// ---------------- split-K reduce ---------------------------------------------
template<bool BIAS>
__global__ void reduce_kernel(const float* __restrict__ part, long slab, int S,
                              float* __restrict__ out, const float* __restrict__ bias,
                              int N, long n4) {
    long i = (long)blockIdx.x * blockDim.x + threadIdx.x;
    if (i >= n4) return;
    float4 s = ((const float4*)part)[i];
    for (int k = 1; k < S; k++) {
        float4 p = ((const float4*)(part + (long)k * slab))[i];
        s.x += p.x; s.y += p.y; s.z += p.z; s.w += p.w;
    }
    if (BIAS) {
        int c = (int)((i * 4) % N);
        s.x += bias[c]; s.y += bias[c + 1]; s.z += bias[c + 2]; s.w += bias[c + 3];
    }
    ((float4*)out)[i] = s;
}

// ---------------- attention scores + softmax (writes split probs) ------------
__global__ void attn_scores_kernel() {
    int bh = blockIdx.x;
    int b = bh / NHEADS, h = bh % NHEADS;
    int t = blockIdx.y * 128 + threadIdx.x;

    __shared__ float kk[TT][DH_QK];
    const float* kbase = g_k + (long)b * TT * NEMBDS + h * DH_QK;
    for (int i = threadIdx.x; i < TT * (DH_QK / 4); i += 128) {
        int row = i >> 2, c4 = i & 3;
        ((float4*)&kk[row][0])[c4] =
            *(const float4*)(kbase + (long)row * NEMBDS + c4 * 4);
    }
    __syncthreads();

    float qv[DH_QK];
    const float* qb = g_q + (long)(b * TT + t) * NEMBDS + h * DH_QK;
#pragma unroll
    for (int d = 0; d < DH_QK; d++) qv[d] = qb[d];

    float* srow = g_scores + ((long)bh * TT + t) * TT;
    float mx = -1e30f;
    for (int tp = 0; tp <= t; tp++) {
        float s = 0.f;
#pragma unroll
        for (int d = 0; d < DH_QK; d++) s += qv[d] * kk[tp][d];
        s *= 0.25f;
        mx = fmaxf(mx, s);
        srow[tp] = s;
    }
    float sum = 0.f;
    for (int tp = 0; tp <= t; tp++) sum += __expf(srow[tp] - mx);
    float inv = 1.f / sum;
    long base = ((long)bh * TT + t) * TT;
    for (int tp = 0; tp < TT; tp++) {
        float p = (tp <= t) ? __expf(srow[tp] - mx) * inv : 0.f;
        __nv_bfloat16 hh, ll; split1(p, hh, ll);
        s_pr[0][base + tp] = hh;
        s_pr[1][base + tp] = ll;
    }
}

// ---------------- projection + residual (writes split x2) --------------------
__global__ void proj_kernel() {
    int m = blockIdx.x;
    int tid = threadIdx.x;
    const float* dz = g_Dz + (long)m * DIMIN;
    const float* x  = g_x  + (long)m * DIMIN;

    float num = 0.f, den = 0.f;
    for (int j = tid; j < DIMIN; j += 256) {
        float a = dz[j], c = x[j];
        num += a * c;
        den += a * a;
    }
#pragma unroll
    for (int o = 16; o > 0; o >>= 1) {
        num += __shfl_down_sync(0xFFFFFFFFu, num, o);
        den += __shfl_down_sync(0xFFFFFFFFu, den, o);
    }
    __shared__ float sn[8], sd[8];
    __shared__ float s_projv;
    int lane = tid & 31, wd = tid >> 5;
    if (lane == 0) { sn[wd] = num; sd[wd] = den; }
    __syncthreads();
    if (tid == 0) {
        float N = 0.f, Dd = 0.f;
#pragma unroll
        for (int i = 0; i < 8; i++) { N += sn[i]; Dd += sd[i]; }
        float p = N / (Dd + EPSV);
        s_projv = p;
        g_proj[m] = p;
    }
    __syncthreads();
    float p = s_projv;
    for (int j = tid; j < DIMIN; j += 256) {
        float v = x[j] - p * dz[j];
        __nv_bfloat16 h, l; split1(v, h, l);
        long o = (long)m * DIMIN + j;
        s_x2[0][o] = h; s_x2[1][o] = l;
    }
}

// ---------------- top-k + z sum (writes split zsum) --------------------------
__global__ void topk_zsum_kernel(const int* __restrict__ kvalp) {
    int m = blockIdx.x;
    int tid = threadIdx.x;

    __shared__ unsigned sv[WIDTH];
    __shared__ int hist[256];
    __shared__ int s_target;
    __shared__ unsigned s_prefix, s_mask;

    const float* zn = g_znov + (long)m * WIDTH;
    for (int j = tid; j < WIDTH; j += 256)
        sv[j] = __float_as_uint(zn[j]);
    if (tid == 0) { s_target = *kvalp; s_prefix = 0u; s_mask = 0u; }
    __syncthreads();

    for (int byte = 3; byte >= 0; --byte) {
        hist[tid] = 0;
        __syncthreads();
        int shift = byte * 8;
        unsigned pm = s_mask, pf = s_prefix;
        for (int j = tid; j < WIDTH; j += 256) {
            unsigned v = sv[j];
            if ((v & pm) == pf) atomicAdd(&hist[(v >> shift) & 255], 1);
        }
        __syncthreads();
        if (tid == 0) {
            int cum = 0, tgt = s_target, sel = 0;
            for (int bin = 255; bin >= 0; --bin) {
                int c = hist[bin];
                if (cum + c >= tgt) { sel = bin; break; }
                cum += c;
            }
            s_target = tgt - cum;
            s_prefix = pf | ((unsigned)sel << shift);
            s_mask   = pm | (0xFFu << shift);
        }
        __syncthreads();
    }
    unsigned tau = s_prefix;
    float p = g_proj[m];
    const float* zp = g_zpred + (long)m * WIDTH;
    for (int j = tid; j < WIDTH; j += 256) {
        unsigned v = sv[j];
        float zval = (v >= tau) ? __uint_as_float(v) : 0.f;
        float o = zval + p * zp[j];
        __nv_bfloat16 h, l; split1(o, h, l);
        long e = (long)m * WIDTH + j;
        s_zs[0][e] = h; s_zs[1][e] = l;
    }
}

// ---------------- launcher ---------------------------------------------------
#define SMEM256 (2 * (32768 + 2 * 256 * 128))   /* 196608 */
#define SMEM128 (3 * (32768 + 2 * 128 * 128))   /* 196608 */

extern "C" void kernel_launch(void* const* d_in, const int* in_sizes, int n_in,
                              void* d_out, int out_size)
{
    const float* x_input = (const float*)d_in[0];
    const float* D       = (const float*)d_in[1];
    const float* bvec    = (const float*)d_in[2];
    const float* Wk      = (const float*)d_in[3];
    const float* bk      = (const float*)d_in[4];
    const float* Wq      = (const float*)d_in[5];
    const float* bq      = (const float*)d_in[6];
    const float* Wv      = (const float*)d_in[7];
    const float* bv      = (const float*)d_in[8];
    const float* Wo      = (const float*)d_in[9];
    const float* bo      = (const float*)d_in[10];
    const int*   kval    = (const int*)d_in[11];

    float *pq, *pk, *pDz, *pzpred, *pznov, *ppart;
    cudaGetSymbolAddress((void**)&pq,     g_q);
    cudaGetSymbolAddress((void**)&pk,     g_k);
    cudaGetSymbolAddress((void**)&pDz,    g_Dz);
    cudaGetSymbolAddress((void**)&pzpred, g_zpred);
    cudaGetSymbolAddress((void**)&pznov,  g_znov);
    cudaGetSymbolAddress((void**)&ppart,  g_part);

    __nv_bfloat16 *pxs, *px2s, *pDs, *pDTs, *pWks, *pWqs, *pWvs, *pWos,
                  *pzins, *pvs, *pvTs, *pprs, *pats, *pzps, *pzss;
    cudaGetSymbolAddress((void**)&pxs,   s_x);
    cudaGetSymbolAddress((void**)&px2s,  s_x2);
    cudaGetSymbolAddress((void**)&pDs,   s_D);
    cudaGetSymbolAddress((void**)&pDTs,  s_DT);
    cudaGetSymbolAddress((void**)&pWks,  s_Wk);
    cudaGetSymbolAddress((void**)&pWqs,  s_Wq);
    cudaGetSymbolAddress((void**)&pWvs,  s_Wv);
    cudaGetSymbolAddress((void**)&pWos,  s_Wo);
    cudaGetSymbolAddress((void**)&pzins, s_zin);
    cudaGetSymbolAddress((void**)&pvs,   s_v);
    cudaGetSymbolAddress((void**)&pvTs,  s_vT);
    cudaGetSymbolAddress((void**)&pprs,  s_pr);
    cudaGetSymbolAddress((void**)&pats,  s_at);
    cudaGetSymbolAddress((void**)&pzps,  s_zp);
    cudaGetSymbolAddress((void**)&pzss,  s_zs);

    cudaFuncSetAttribute(tgemm<256, true,  false, false, 1>, cudaFuncAttributeMaxDynamicSharedMemorySize, SMEM256);
    cudaFuncSetAttribute(tgemm<128, false, false, true,  0>, cudaFuncAttributeMaxDynamicSharedMemorySize, SMEM128);
    cudaFuncSetAttribute(tgemm<128, false, false, false, 0>, cudaFuncAttributeMaxDynamicSharedMemorySize, SMEM128);
    cudaFuncSetAttribute(tgemm<256, false, true,  true,  1>, cudaFuncAttributeMaxDynamicSharedMemorySize, SMEM256);
    cudaFuncSetAttribute(tgemm<256, false, false, false, 1>, cudaFuncAttributeMaxDynamicSharedMemorySize, SMEM256);
    cudaFuncSetAttribute(tgemm<256, true,  true,  false, 2>, cudaFuncAttributeMaxDynamicSharedMemorySize, SMEM256);
    cudaFuncSetAttribute(tgemm<256, false, false, false, 0>, cudaFuncAttributeMaxDynamicSharedMemorySize, SMEM256);
    cudaFuncSetAttribute(tgemm<256, true,  false, false, 0>, cudaFuncAttributeMaxDynamicSharedMemorySize, SMEM256);

    // ---- input prep + weight splits ----
    prep_kernel<<<(MM * (DIMIN / 4) + 255) / 256, 256>>>(x_input, bvec);
    wsplit_kernel<<<((long)WIDTH * DIMIN / 4 + 255) / 256, 256>>>(D,  pDs,  pDs  + (long)WIDTH * DIMIN,  (long)WIDTH * DIMIN / 4);
    wsplit_kernel<<<((long)NEMBDS * WIDTH / 4 + 255) / 256, 256>>>(Wk, pWks, pWks + (long)NEMBDS * WIDTH, (long)NEMBDS * WIDTH / 4);
    wsplit_kernel<<<((long)NEMBDS * WIDTH / 4 + 255) / 256, 256>>>(Wq, pWqs, pWqs + (long)NEMBDS * WIDTH, (long)NEMBDS * WIDTH / 4);
    wsplit_kernel<<<((long)WIDTH * WIDTH / 4 + 255) / 256, 256>>>(Wv, pWvs, pWvs + (long)WIDTH * WIDTH, (long)WIDTH * WIDTH / 4);
    wsplit_kernel<<<((long)WIDTH * WIDTH / 4 + 255) / 256, 256>>>(Wo, pWos, pWos + (long)WIDTH * WIDTH, (long)WIDTH * WIDTH / 4);
    dtsplit_kernel<<<dim3(DIMIN / 32, WIDTH / 32), dim3(32, 8)>>>(D);

    const long NW = (long)MM * WIDTH;
    const long ND = (long)MM * DIMIN;
    const long NE = (long)NEMBDS * WIDTH;
    const long WW = (long)WIDTH * WIDTH;
    const long WD = (long)WIDTH * DIMIN;
    const long PP = (long)BB * NHEADS * TT * TT;

    // 2) z_in = relu(lam * x @ D^T)  -> split
    tgemm<256, true, false, false, 1><<<dim3(WIDTH / 256, MM / 128, 1), 256, SMEM256>>>(
        pxs, pxs + ND, DIMIN, pDs, pDs + WD, DIMIN,
        nullptr, pzins, pzins + NW, WIDTH, DIMIN, LAM, nullptr, 0, 0, 1, 0, 0);

    // 3) k partials (shifted A), split-K 8 -> reduce + bk
    tgemm<128, false, false, true, 0><<<dim3(1, MM / 128, 8), 256, SMEM128>>>(
        pzins, pzins + NW, WIDTH, pWks, pWks + NE, WIDTH,
        ppart, nullptr, nullptr, NEMBDS, WIDTH / 8, 1.f, nullptr,
        WIDTH / 8, WIDTH / 8, 1, (long)MM * NEMBDS, 0);
    reduce_kernel<true><<<((long)MM * NEMBDS / 4 + 255) / 256, 256>>>(
        ppart, (long)MM * NEMBDS, 8, pk, bk, NEMBDS, (long)MM * NEMBDS / 4);

    // 4) q partials, split-K 8 -> reduce + bq
    tgemm<128, false, false, false, 0><<<dim3(1, MM / 128, 8), 256, SMEM128>>>(
        pzins, pzins + NW, WIDTH, pWqs, pWqs + NE, WIDTH,
        ppart, nullptr, nullptr, NEMBDS, WIDTH / 8, 1.f, nullptr,
        WIDTH / 8, WIDTH / 8, 1, (long)MM * NEMBDS, 0);
    reduce_kernel<true><<<((long)MM * NEMBDS / 4 + 255) / 256, 256>>>(
        ppart, (long)MM * NEMBDS, 8, pq, bq, NEMBDS, (long)MM * NEMBDS / 4);

    // 5) v = shift(z_in) @ Wv^T + bv  -> split, then transpose
    tgemm<256, false, true, true, 1><<<dim3(WIDTH / 256, MM / 128, 1), 256, SMEM256>>>(
        pzins, pzins + NW, WIDTH, pWvs, pWvs + WW, WIDTH,
        nullptr, pvs, pvs + NW, WIDTH, WIDTH, 1.f, bv, 0, 0, 1, 0, 0);
    vtrans_kernel<<<dim3(WIDTH / 32, TT / 32, BB), dim3(32, 8)>>>();

    // 6) scores + softmax -> split probs
    attn_scores_kernel<<<dim3(BB * NHEADS, TT / 128), 128>>>();

    // 7) o = P @ V^T per (b,h) -> split attno
    tgemm<256, false, false, false, 1><<<dim3(DH_V / 256, TT / 128, BB * NHEADS), 256, SMEM256>>>(
        pprs, pprs + PP, TT, pvTs, pvTs + NW, TT,
        nullptr, pats, pats + NW, WIDTH, TT, 1.f, nullptr,
        (long)TT * TT, (long)DH_V * TT, NHEADS, (long)TT * WIDTH, (long)DH_V);

    // 8) z_pred_ = relu(o @ Wo^T + bo) -> fp32 + split
    tgemm<256, true, true, false, 2><<<dim3(WIDTH / 256, MM / 128, 1), 256, SMEM256>>>(
        pats, pats + NW, WIDTH, pWos, pWos + WW, WIDTH,
        pzpred, pzps, pzps + NW, WIDTH, WIDTH, 1.f, bo, 0, 0, 1, 0, 0);

    // 9) Dz = z_pred_ @ D  (via DT), split-K 2 -> reduce
    tgemm<256, false, false, false, 0><<<dim3(DIMIN / 256, MM / 128, 2), 256, SMEM256>>>(
        pzps, pzps + NW, WIDTH, pDTs, pDTs + WD, WIDTH,
        ppart, nullptr, nullptr, DIMIN, WIDTH / 2, 1.f, nullptr,
        WIDTH / 2, WIDTH / 2, 1, ND, 0);
    reduce_kernel<false><<<(ND / 4 + 255) / 256, 256>>>(
        ppart, ND, 2, pDz, nullptr, DIMIN, ND / 4);

    // 10) proj + residual -> split x2
    proj_kernel<<<MM, 256>>>();

    // 11) z_novel = relu(lam * x2 @ D^T) -> fp32
    tgemm<256, true, false, false, 0><<<dim3(WIDTH / 256, MM / 128, 1), 256, SMEM256>>>(
        px2s, px2s + ND, DIMIN, pDs, pDs + WD, DIMIN,
        pznov, nullptr, nullptr, WIDTH, DIMIN, LAM, nullptr, 0, 0, 1, 0, 0);

    // 12) top-k + z sum -> split zsum
    topk_zsum_kernel<<<MM, 256>>>(kval);

    // 13) x_recons = zsum @ D + b (via DT), split-K 2 -> reduce + bvec -> d_out
    tgemm<256, false, false, false, 0><<<dim3(DIMIN / 256, MM / 128, 2), 256, SMEM256>>>(
        pzss, pzss + NW, WIDTH, pDTs, pDTs + WD, WIDTH,
        ppart, nullptr, nullptr, DIMIN, WIDTH / 2, 1.f, nullptr,
        WIDTH / 2, WIDTH / 2, 1, ND, 0);
    reduce_kernel<true><<<(ND / 4 + 255) / 256, 256>>>(
        ppart, ND, 2, (float*)d_out, bvec, DIMIN, ND / 4);
}

// round 7
// speedup vs baseline: 1.3042x; 1.3042x over previous
#include <cuda_runtime.h>
#include <cuda_bf16.h>
#include <math.h>

#define BB      8
#define TT      512
#define DIMIN   768
#define WIDTH   8192
#define NHEADS  8
#define NEMBDS  128
#define DH_QK   16
#define DH_V    1024
#define MM      (BB * TT)          /* 4096 */
#define LAM     (1.0f / 3072.0f)
#define EPSV    1e-6f
#define KT      64                 /* K-tile elems (128B bf16 rows) */

// ---------------- fp32 scratch ----------------------------------------------
__device__ float g_x     [MM * DIMIN];
__device__ float g_q     [MM * NEMBDS];
__device__ float g_k     [MM * NEMBDS];
__device__ float g_scores[(long)BB * NHEADS * TT * TT];
__device__ float g_Dz    [MM * DIMIN];
__device__ float g_zpred [MM * WIDTH];
__device__ float g_znov  [MM * WIDTH];
__device__ float g_proj  [MM];
__device__ float g_part  [2 * MM * DIMIN];           /* >= 8*MM*NEMBDS */

// ---------------- bf16 hi/lo split buffers ([0]=hi, [1]=lo) ------------------
__device__ __align__(256) __nv_bfloat16 s_x    [2][MM * DIMIN];
__device__ __align__(256) __nv_bfloat16 s_x2   [2][MM * DIMIN];
__device__ __align__(256) __nv_bfloat16 s_D    [2][WIDTH * DIMIN];
__device__ __align__(256) __nv_bfloat16 s_DT   [2][DIMIN * WIDTH];
__device__ __align__(256) __nv_bfloat16 s_Wk   [2][NEMBDS * WIDTH];
__device__ __align__(256) __nv_bfloat16 s_Wq   [2][NEMBDS * WIDTH];
__device__ __align__(256) __nv_bfloat16 s_Wv   [2][WIDTH * WIDTH];
__device__ __align__(256) __nv_bfloat16 s_Wo   [2][WIDTH * WIDTH];
__device__ __align__(256) __nv_bfloat16 s_zin  [2][MM * WIDTH];
__device__ __align__(256) __nv_bfloat16 s_v    [2][MM * WIDTH];
__device__ __align__(256) __nv_bfloat16 s_vT   [2][MM * WIDTH];
__device__ __align__(256) __nv_bfloat16 s_pr   [2][(long)BB * NHEADS * TT * TT];
__device__ __align__(256) __nv_bfloat16 s_at   [2][MM * WIDTH];
__device__ __align__(256) __nv_bfloat16 s_zp   [2][MM * WIDTH];
__device__ __align__(256) __nv_bfloat16 s_zs   [2][MM * WIDTH];

// ---------------- helpers ----------------------------------------------------
__device__ __forceinline__ unsigned smem_u32(const void* p) {
    unsigned a;
    asm("{ .reg .u64 t; cvta.to.shared.u64 t, %1; cvt.u32.u64 %0, t; }"
        : "=r"(a) : "l"(p));
    return a;
}
__device__ __forceinline__ unsigned swz(unsigned off) {
    return off ^ ((off >> 3) & 0x70);
}
__device__ __forceinline__ void cpa(unsigned dst, const void* src, int sz) {
    asm volatile("cp.async.cg.shared.global [%0], [%1], 16, %2;"
                 :: "r"(dst), "l"(src), "r"(sz) : "memory");
}
#define CPA_COMMIT() asm volatile("cp.async.commit_group;" ::: "memory")
#define CPA_WAIT1()  asm volatile("cp.async.wait_group 1;" ::: "memory")
#define CPA_WAIT0()  asm volatile("cp.async.wait_group 0;" ::: "memory")

#define LDSM4(r, a)                                                             \
    asm volatile("ldmatrix.sync.aligned.m8n8.x4.shared.b16 {%0,%1,%2,%3},[%4];" \
                 : "=r"((r)[0]), "=r"((r)[1]), "=r"((r)[2]), "=r"((r)[3])       \
                 : "r"(a))
#define MMA(d, a, b)                                                            \
    asm volatile("mma.sync.aligned.m16n8k16.row.col.f32.bf16.bf16.f32 "         \
                 "{%0,%1,%2,%3},{%4,%5,%6,%7},{%8,%9},{%0,%1,%2,%3};"           \
                 : "+f"((d)[0]), "+f"((d)[1]), "+f"((d)[2]), "+f"((d)[3])       \
                 : "r"((a)[0]), "r"((a)[1]), "r"((a)[2]), "r"((a)[3]),          \
                   "r"((b)[0]), "r"((b)[1]))

__device__ __forceinline__ void split1(float v, __nv_bfloat16& h, __nv_bfloat16& l) {
    h = __float2bfloat16(v);
    l = __float2bfloat16(v - __bfloat162float(h));
}

// ---------------- GEMM: pre-split bf16 operands, cp.async pipeline -----------
// 512 threads, 16 warps (4x4 warp grid), warp tile 32 x (NTILE/4).
// C = act(alpha * A @ B^T + bias), A (M x K) hi/lo, B (N x K) hi/lo, row-major.
// EPI: 0 = fp32, 1 = split, 2 = both.
template<int NTILE, bool RELU, bool BIAS, bool SHIFT, int EPI>
__global__ void __launch_bounds__(512, 1) tgemm(
    const __nv_bfloat16* __restrict__ Ah, const __nv_bfloat16* __restrict__ Al, int lda,
    const __nv_bfloat16* __restrict__ Bh, const __nv_bfloat16* __restrict__ Bl, int ldb,
    float* __restrict__ Cf, __nv_bfloat16* __restrict__ Ch, __nv_bfloat16* __restrict__ Cl,
    int ldc, int K, float alpha, const float* __restrict__ bias,
    long sA, long sB, int zdiv, long sCo, long sCi)
{
    constexpr int NST  = (NTILE == 256) ? 2 : 3;   // stages (96KB / 64KB each)
    constexpr int BBYT = NTILE * 128;              // B hi bytes per stage
    constexpr int STBY = 32768 + 2 * BBYT;
    constexpr int NG   = NTILE / 64;               // n16-groups per warp
    constexpr int NWT  = 2 * NG;                   // n8-frags per warp

    extern __shared__ char sm[];
    const unsigned sb = smem_u32(sm);
    const int tid = threadIdx.x, wid = tid >> 5, lane = tid & 31;

    const int z = blockIdx.z;
    Ah += (long)z * sA;  Al += (long)z * sA;
    Bh += (long)z * sB;  Bl += (long)z * sB;
    const long coff = (long)(z / zdiv) * sCo + (long)(z % zdiv) * sCi;

    const int m0 = blockIdx.y * 128;
    const int n0 = blockIdx.x * NTILE;
    const int mw = (wid & 3) * 32;                 // warp m offset
    const int nw = (wid >> 2) * (NTILE / 4);       // warp n offset

    float acc[2][NWT][4];
#pragma unroll
    for (int i = 0; i < 2; i++)
#pragma unroll
        for (int j = 0; j < NWT; j++)
#pragma unroll
            for (int l = 0; l < 4; l++) acc[i][j][l] = 0.f;

    const int nkt = K / KT;

    auto issue = [&](int kt) {
        const unsigned st = sb + (kt % NST) * STBY;
#pragma unroll
        for (int i = 0; i < 2; i++) {               // A: 1024 chunks
            int idx = i * 512 + tid;
            int row = idx >> 3, c = idx & 7;
            unsigned d = st + swz(row * 128 + c * 16);
            long off; int sz = 16;
            if (SHIFT) {
                int gr = m0 + row;
                int ok = (gr & (TT - 1)) != 0;
                off = (long)(ok ? gr - 1 : 0) * lda + kt * KT + c * 8;
                sz = ok ? 16 : 0;
            } else {
                off = (long)(m0 + row) * lda + kt * KT + c * 8;
            }
            cpa(d,         Ah + off, sz);
            cpa(d + 16384, Al + off, sz);
        }
#pragma unroll
        for (int i = 0; i < NTILE / 64; i++) {      // B: NTILE*8 chunks
            int idx = i * 512 + tid;
            int row = idx >> 3, c = idx & 7;
            unsigned d = st + 32768 + swz(row * 128 + c * 16);
            long off = (long)(n0 + row) * ldb + kt * KT + c * 8;
            cpa(d,        Bh + off, 16);
            cpa(d + BBYT, Bl + off, 16);
        }
        CPA_COMMIT();
    };

    issue(0);
    issue(1);

    const int frow = lane & 15, fch = lane >> 4;   // shared ldsm addressing

    for (int kt = 0; kt < nkt; kt++) {
        if (kt == nkt - 1) { CPA_WAIT0(); } else { CPA_WAIT1(); }
        __syncthreads();

        const unsigned st  = sb + (kt % NST) * STBY;
        const unsigned ahb = st, alb = st + 16384;
        const unsigned bhb = st + 32768, blb = st + 32768 + BBYT;
#pragma unroll
        for (int ks = 0; ks < 4; ks++) {
            unsigned ah[2][4], al[2][4];
#pragma unroll
            for (int mt = 0; mt < 2; mt++) {
                unsigned o = swz((mw + mt * 16 + frow) * 128 + ks * 32 + 16 * fch);
                LDSM4(ah[mt], ahb + o);
                LDSM4(al[mt], alb + o);
            }
#pragma unroll
            for (int g = 0; g < NG; g++) {
                unsigned o = swz((nw + g * 16 + frow) * 128 + ks * 32 + 16 * fch);
                unsigned rb[4], rl[4];
                LDSM4(rb, bhb + o);
                LDSM4(rl, blb + o);
                unsigned bh0[2] = {rb[0], rb[2]}, bh1[2] = {rb[1], rb[3]};
                unsigned bl0[2] = {rl[0], rl[2]}, bl1[2] = {rl[1], rl[3]};
#pragma unroll
                for (int mt = 0; mt < 2; mt++) {
                    MMA(acc[mt][2 * g],     ah[mt], bh0);
                    MMA(acc[mt][2 * g],     ah[mt], bl0);
                    MMA(acc[mt][2 * g],     al[mt], bh0);
                    MMA(acc[mt][2 * g + 1], ah[mt], bh1);
                    MMA(acc[mt][2 * g + 1], ah[mt], bl1);
                    MMA(acc[mt][2 * g + 1], al[mt], bh1);
                }
            }
        }
        __syncthreads();
        if (kt + 2 < nkt) issue(kt + 2);
    }

    // ---- epilogue ----
#pragma unroll
    for (int mt = 0; mt < 2; mt++) {
        int r0 = m0 + mw + mt * 16 + (lane >> 2);
#pragma unroll
        for (int nt = 0; nt < NWT; nt++) {
            int c = n0 + nw + nt * 8 + (lane & 3) * 2;
            float b0 = BIAS ? bias[c] : 0.f;
            float b1 = BIAS ? bias[c + 1] : 0.f;
#pragma unroll
            for (int half = 0; half < 2; half++) {
                int r = r0 + half * 8;
                float v0 = alpha * acc[mt][nt][half * 2 + 0] + b0;
                float v1 = alpha * acc[mt][nt][half * 2 + 1] + b1;
                if (RELU) { v0 = fmaxf(v0, 0.f); v1 = fmaxf(v1, 0.f); }
                long e = coff + (long)r * ldc + c;
                if (EPI == 0 || EPI == 2)
                    *(float2*)(Cf + e) = make_float2(v0, v1);
                if (EPI == 1 || EPI == 2) {
                    __nv_bfloat162 h = __floats2bfloat162_rn(v0, v1);
                    float r0f = v0 - __bfloat162float(h.x);
                    float r1f = v1 - __bfloat162float(h.y);
                    __nv_bfloat162 l = __floats2bfloat162_rn(r0f, r1f);
                    *(__nv_bfloat162*)(Ch + e) = h;
                    *(__nv_bfloat162*)(Cl + e) = l;
                }
            }
        }
    }
}

// ---------------- split / transpose kernels ----------------------------------
__global__ void wsplit_kernel(const float* __restrict__ in,
                              __nv_bfloat16* __restrict__ hi,
                              __nv_bfloat16* __restrict__ lo, long n4) {
    long i = (long)blockIdx.x * blockDim.x + threadIdx.x;
    if (i >= n4) return;
    float4 v = ((const float4*)in)[i];
    __nv_bfloat162 h01 = __floats2bfloat162_rn(v.x, v.y);
    __nv_bfloat162 h23 = __floats2bfloat162_rn(v.z, v.w);
    __nv_bfloat162 l01 = __floats2bfloat162_rn(v.x - __bfloat162float(h01.x),
                                               v.y - __bfloat162float(h01.y));
    __nv_bfloat162 l23 = __floats2bfloat162_rn(v.z - __bfloat162float(h23.x),
                                               v.w - __bfloat162float(h23.y));
    ((uint2*)hi)[i] = make_uint2(*(unsigned*)&h01, *(unsigned*)&h23);
    ((uint2*)lo)[i] = make_uint2(*(unsigned*)&l01, *(unsigned*)&l23);
}

__global__ void prep_kernel(const float* __restrict__ xin,
                            const float* __restrict__ bvec) {
    long i = (long)blockIdx.x * blockDim.x + threadIdx.x;
    if (i >= MM * (DIMIN / 4)) return;
    int c4 = (int)(i % (DIMIN / 4));
    float4 xv = ((const float4*)xin)[i];
    float4 bv = ((const float4*)bvec)[c4];
    float4 r = make_float4(xv.x - bv.x, xv.y - bv.y, xv.z - bv.z, xv.w - bv.w);
    ((float4*)g_x)[i] = r;
    __nv_bfloat162 h01 = __floats2bfloat162_rn(r.x, r.y);
    __nv_bfloat162 h23 = __floats2bfloat162_rn(r.z, r.w);
    __nv_bfloat162 l01 = __floats2bfloat162_rn(r.x - __bfloat162float(h01.x),
                                               r.y - __bfloat162float(h01.y));
    __nv_bfloat162 l23 = __floats2bfloat162_rn(r.z - __bfloat162float(h23.x),
                                               r.w - __bfloat162float(h23.y));
    ((uint2*)&s_x[0][0])[i] = make_uint2(*(unsigned*)&h01, *(unsigned*)&h23);
    ((uint2*)&s_x[1][0])[i] = make_uint2(*(unsigned*)&l01, *(unsigned*)&l23);
}

// DT[n][k] = D[k][n], split  (D: WIDTH x DIMIN)
__global__ void dtsplit_kernel(const float* __restrict__ D) {
    __shared__ float tl[32][33];
    int n0 = blockIdx.x * 32, k0 = blockIdx.y * 32;
    int tx = threadIdx.x, ty = threadIdx.y;     // (32, 8)
#pragma unroll
    for (int j = 0; j < 4; j++)
        tl[ty + j * 8][tx] = D[(long)(k0 + ty + j * 8) * DIMIN + n0 + tx];
    __syncthreads();
#pragma unroll
    for (int j = 0; j < 4; j++) {
        int nr = ty + j * 8;
        float v = tl[tx][nr];
        __nv_bfloat16 h, l; split1(v, h, l);
        long o = (long)(n0 + nr) * WIDTH + k0 + tx;
        s_DT[0][o] = h; s_DT[1][o] = l;
    }
}

// vT[(b*8+h)*1024+d][t] = v[b*512+t][h*1024+d]
__global__ void vtrans_kernel() {
    __shared__ __nv_bfloat16 tl[2][32][33];
    int b = blockIdx.z;
    int d0 = blockIdx.x * 32;
    int t0 = blockIdx.y * 32;
    int tx = threadIdx.x, ty = threadIdx.y;   // (32, 8)
#pragma unroll
    for (int j = 0; j < 4; j++) {
        int r = ty + j * 8;
        long src = (long)(b * TT + t0 + r) * WIDTH + d0 + tx;
        tl[0][r][tx] = s_v[0][src];
        tl[1][r][tx] = s_v[1][src];
    }
    __syncthreads();
    int h = d0 >> 10, dbase = d0 & 1023;
#pragma unroll
    for (int j = 0; j < 4; j++) {
        int dr = ty + j * 8;
        long orow = (long)(b * NHEADS + h) * DH_V + dbase + dr;
        long dst = orow * TT + t0 + tx;
        s_vT[0][dst] = tl[0][tx][dr];
        s_vT[1][dst] = tl[1][tx][dr];
    }
}

// ---------------- split-K reduce ---------------------------------------------
template<bool BIAS>
__global__ void reduce_kernel(const float* __restrict__ part, long slab, int S,
                              float* __restrict__ out, const float* __restrict__ bias,
                              int N, long n4) {
    long i = (long)blockIdx.x * blockDim.x + threadIdx.x;
    if (i >= n4) return;
    float4 s = ((const float4*)part)[i];
    for (int k = 1; k < S; k++) {
        float4 p = ((const float4*)(part + (long)k * slab))[i];
        s.x += p.x; s.y += p.y; s.z += p.z; s.w += p.w;
    }
    if (BIAS) {
        int c = (int)((i * 4) % N);
        s.x += bias[c]; s.y += bias[c + 1]; s.z += bias[c + 2]; s.w += bias[c + 3];
    }
    ((float4*)out)[i] = s;
}

// ---------------- attention scores + softmax (writes split probs) ------------
__global__ void attn_scores_kernel() {
    int bh = blockIdx.x;
    int b = bh / NHEADS, h = bh % NHEADS;
    int t = blockIdx.y * 128 + threadIdx.x;

    __shared__ float kk[TT][DH_QK];
    const float* kbase = g_k + (long)b * TT * NEMBDS + h * DH_QK;
    for (int i = threadIdx.x; i < TT * (DH_QK / 4); i += 128) {
        int row = i >> 2, c4 = i & 3;
        ((float4*)&kk[row][0])[c4] =
            *(const float4*)(kbase + (long)row * NEMBDS + c4 * 4);
    }
    __syncthreads();

    float qv[DH_QK];
    const float* qb = g_q + (long)(b * TT + t) * NEMBDS + h * DH_QK;
#pragma unroll
    for (int d = 0; d < DH_QK; d++) qv[d] = qb[d];

    float* srow = g_scores + ((long)bh * TT + t) * TT;
    float mx = -1e30f;
    for (int tp = 0; tp <= t; tp++) {
        float s = 0.f;
#pragma unroll
        for (int d = 0; d < DH_QK; d++) s += qv[d] * kk[tp][d];
        s *= 0.25f;
        mx = fmaxf(mx, s);
        srow[tp] = s;
    }
    float sum = 0.f;
    for (int tp = 0; tp <= t; tp++) sum += __expf(srow[tp] - mx);
    float inv = 1.f / sum;
    long base = ((long)bh * TT + t) * TT;
    for (int tp = 0; tp < TT; tp++) {
        float p = (tp <= t) ? __expf(srow[tp] - mx) * inv : 0.f;
        __nv_bfloat16 hh, ll; split1(p, hh, ll);
        s_pr[0][base + tp] = hh;
        s_pr[1][base + tp] = ll;
    }
}

// ---------------- projection + residual (writes split x2) --------------------
__global__ void proj_kernel() {
    int m = blockIdx.x;
    int tid = threadIdx.x;
    const float* dz = g_Dz + (long)m * DIMIN;
    const float* x  = g_x  + (long)m * DIMIN;

    float num = 0.f, den = 0.f;
    for (int j = tid; j < DIMIN; j += 256) {
        float a = dz[j], c = x[j];
        num += a * c;
        den += a * a;
    }
#pragma unroll
    for (int o = 16; o > 0; o >>= 1) {
        num += __shfl_down_sync(0xFFFFFFFFu, num, o);
        den += __shfl_down_sync(0xFFFFFFFFu, den, o);
    }
    __shared__ float sn[8], sd[8];
    __shared__ float s_projv;
    int lane = tid & 31, wd = tid >> 5;
    if (lane == 0) { sn[wd] = num; sd[wd] = den; }
    __syncthreads();
    if (tid == 0) {
        float N = 0.f, Dd = 0.f;
#pragma unroll
        for (int i = 0; i < 8; i++) { N += sn[i]; Dd += sd[i]; }
        float p = N / (Dd + EPSV);
        s_projv = p;
        g_proj[m] = p;
    }
    __syncthreads();
    float p = s_projv;
    for (int j = tid; j < DIMIN; j += 256) {
        float v = x[j] - p * dz[j];
        __nv_bfloat16 h, l; split1(v, h, l);
        long o = (long)m * DIMIN + j;
        s_x2[0][o] = h; s_x2[1][o] = l;
    }
}

// ---------------- top-k + z sum (writes split zsum) --------------------------
__global__ void topk_zsum_kernel(const int* __restrict__ kvalp) {
    int m = blockIdx.x;
    int tid = threadIdx.x;

    __shared__ unsigned sv[WIDTH];
    __shared__ int hist[256];
    __shared__ int s_target;
    __shared__ unsigned s_prefix, s_mask;

    const float* zn = g_znov + (long)m * WIDTH;
    for (int j = tid; j < WIDTH; j += 256)
        sv[j] = __float_as_uint(zn[j]);
    if (tid == 0) { s_target = *kvalp; s_prefix = 0u; s_mask = 0u; }
    __syncthreads();

    for (int byte = 3; byte >= 0; --byte) {
        hist[tid] = 0;
        __syncthreads();
        int shift = byte * 8;
        unsigned pm = s_mask, pf = s_prefix;
        for (int j = tid; j < WIDTH; j += 256) {
            unsigned v = sv[j];
            if ((v & pm) == pf) atomicAdd(&hist[(v >> shift) & 255], 1);
        }
        __syncthreads();
        if (tid == 0) {
            int cum = 0, tgt = s_target, sel = 0;
            for (int bin = 255; bin >= 0; --bin) {
                int c = hist[bin];
                if (cum + c >= tgt) { sel = bin; break; }
                cum += c;
            }
            s_target = tgt - cum;
            s_prefix = pf | ((unsigned)sel << shift);
            s_mask   = pm | (0xFFu << shift);
        }
        __syncthreads();
    }
    unsigned tau = s_prefix;
    float p = g_proj[m];
    const float* zp = g_zpred + (long)m * WIDTH;
    for (int j = tid; j < WIDTH; j += 256) {
        unsigned v = sv[j];
        float zval = (v >= tau) ? __uint_as_float(v) : 0.f;
        float o = zval + p * zp[j];
        __nv_bfloat16 h, l; split1(o, h, l);
        long e = (long)m * WIDTH + j;
        s_zs[0][e] = h; s_zs[1][e] = l;
    }
}

// ---------------- launcher ---------------------------------------------------
#define SMEM256 (2 * (32768 + 2 * 256 * 128))   /* 196608 */
#define SMEM128 (3 * (32768 + 2 * 128 * 128))   /* 196608 */

extern "C" void kernel_launch(void* const* d_in, const int* in_sizes, int n_in,
                              void* d_out, int out_size)
{
    const float* x_input = (const float*)d_in[0];
    const float* D       = (const float*)d_in[1];
    const float* bvec    = (const float*)d_in[2];
    const float* Wk      = (const float*)d_in[3];
    const float* bk      = (const float*)d_in[4];
    const float* Wq      = (const float*)d_in[5];
    const float* bq      = (const float*)d_in[6];
    const float* Wv      = (const float*)d_in[7];
    const float* bv      = (const float*)d_in[8];
    const float* Wo      = (const float*)d_in[9];
    const float* bo      = (const float*)d_in[10];
    const int*   kval    = (const int*)d_in[11];

    float *pq, *pk, *pDz, *pzpred, *pznov, *ppart;
    cudaGetSymbolAddress((void**)&pq,     g_q);
    cudaGetSymbolAddress((void**)&pk,     g_k);
    cudaGetSymbolAddress((void**)&pDz,    g_Dz);
    cudaGetSymbolAddress((void**)&pzpred, g_zpred);
    cudaGetSymbolAddress((void**)&pznov,  g_znov);
    cudaGetSymbolAddress((void**)&ppart,  g_part);

    __nv_bfloat16 *pxs, *px2s, *pDs, *pDTs, *pWks, *pWqs, *pWvs, *pWos,
                  *pzins, *pvs, *pvTs, *pprs, *pats, *pzps, *pzss;
    cudaGetSymbolAddress((void**)&pxs,   s_x);
    cudaGetSymbolAddress((void**)&px2s,  s_x2);
    cudaGetSymbolAddress((void**)&pDs,   s_D);
    cudaGetSymbolAddress((void**)&pDTs,  s_DT);
    cudaGetSymbolAddress((void**)&pWks,  s_Wk);
    cudaGetSymbolAddress((void**)&pWqs,  s_Wq);
    cudaGetSymbolAddress((void**)&pWvs,  s_Wv);
    cudaGetSymbolAddress((void**)&pWos,  s_Wo);
    cudaGetSymbolAddress((void**)&pzins, s_zin);
    cudaGetSymbolAddress((void**)&pvs,   s_v);
    cudaGetSymbolAddress((void**)&pvTs,  s_vT);
    cudaGetSymbolAddress((void**)&pprs,  s_pr);
    cudaGetSymbolAddress((void**)&pats,  s_at);
    cudaGetSymbolAddress((void**)&pzps,  s_zp);
    cudaGetSymbolAddress((void**)&pzss,  s_zs);

    cudaFuncSetAttribute(tgemm<256, true,  false, false, 1>, cudaFuncAttributeMaxDynamicSharedMemorySize, SMEM256);
    cudaFuncSetAttribute(tgemm<128, false, false, true,  0>, cudaFuncAttributeMaxDynamicSharedMemorySize, SMEM128);
    cudaFuncSetAttribute(tgemm<128, false, false, false, 0>, cudaFuncAttributeMaxDynamicSharedMemorySize, SMEM128);
    cudaFuncSetAttribute(tgemm<256, false, true,  true,  1>, cudaFuncAttributeMaxDynamicSharedMemorySize, SMEM256);
    cudaFuncSetAttribute(tgemm<256, false, false, false, 1>, cudaFuncAttributeMaxDynamicSharedMemorySize, SMEM256);
    cudaFuncSetAttribute(tgemm<256, true,  true,  false, 2>, cudaFuncAttributeMaxDynamicSharedMemorySize, SMEM256);
    cudaFuncSetAttribute(tgemm<256, false, false, false, 0>, cudaFuncAttributeMaxDynamicSharedMemorySize, SMEM256);
    cudaFuncSetAttribute(tgemm<256, true,  false, false, 0>, cudaFuncAttributeMaxDynamicSharedMemorySize, SMEM256);

    // ---- input prep + weight splits ----
    prep_kernel<<<(MM * (DIMIN / 4) + 255) / 256, 256>>>(x_input, bvec);
    wsplit_kernel<<<((long)WIDTH * DIMIN / 4 + 255) / 256, 256>>>(D,  pDs,  pDs  + (long)WIDTH * DIMIN,  (long)WIDTH * DIMIN / 4);
    wsplit_kernel<<<((long)NEMBDS * WIDTH / 4 + 255) / 256, 256>>>(Wk, pWks, pWks + (long)NEMBDS * WIDTH, (long)NEMBDS * WIDTH / 4);
    wsplit_kernel<<<((long)NEMBDS * WIDTH / 4 + 255) / 256, 256>>>(Wq, pWqs, pWqs + (long)NEMBDS * WIDTH, (long)NEMBDS * WIDTH / 4);
    wsplit_kernel<<<((long)WIDTH * WIDTH / 4 + 255) / 256, 256>>>(Wv, pWvs, pWvs + (long)WIDTH * WIDTH, (long)WIDTH * WIDTH / 4);
    wsplit_kernel<<<((long)WIDTH * WIDTH / 4 + 255) / 256, 256>>>(Wo, pWos, pWos + (long)WIDTH * WIDTH, (long)WIDTH * WIDTH / 4);
    dtsplit_kernel<<<dim3(DIMIN / 32, WIDTH / 32), dim3(32, 8)>>>(D);

    const long NW = (long)MM * WIDTH;
    const long ND = (long)MM * DIMIN;
    const long NE = (long)NEMBDS * WIDTH;
    const long WW = (long)WIDTH * WIDTH;
    const long WD = (long)WIDTH * DIMIN;
    const long PP = (long)BB * NHEADS * TT * TT;

    // 2) z_in = relu(lam * x @ D^T)  -> split
    tgemm<256, true, false, false, 1><<<dim3(WIDTH / 256, MM / 128, 1), 512, SMEM256>>>(
        pxs, pxs + ND, DIMIN, pDs, pDs + WD, DIMIN,
        nullptr, pzins, pzins + NW, WIDTH, DIMIN, LAM, nullptr, 0, 0, 1, 0, 0);

    // 3) k partials (shifted A), split-K 8 -> reduce + bk
    tgemm<128, false, false, true, 0><<<dim3(1, MM / 128, 8), 512, SMEM128>>>(
        pzins, pzins + NW, WIDTH, pWks, pWks + NE, WIDTH,
        ppart, nullptr, nullptr, NEMBDS, WIDTH / 8, 1.f, nullptr,
        WIDTH / 8, WIDTH / 8, 1, (long)MM * NEMBDS, 0);
    reduce_kernel<true><<<((long)MM * NEMBDS / 4 + 255) / 256, 256>>>(
        ppart, (long)MM * NEMBDS, 8, pk, bk, NEMBDS, (long)MM * NEMBDS / 4);

    // 4) q partials, split-K 8 -> reduce + bq
    tgemm<128, false, false, false, 0><<<dim3(1, MM / 128, 8), 512, SMEM128>>>(
        pzins, pzins + NW, WIDTH, pWqs, pWqs + NE, WIDTH,
        ppart, nullptr, nullptr, NEMBDS, WIDTH / 8, 1.f, nullptr,
        WIDTH / 8, WIDTH / 8, 1, (long)MM * NEMBDS, 0);
    reduce_kernel<true><<<((long)MM * NEMBDS / 4 + 255) / 256, 256>>>(
        ppart, (long)MM * NEMBDS, 8, pq, bq, NEMBDS, (long)MM * NEMBDS / 4);

    // 5) v = shift(z_in) @ Wv^T + bv  -> split, then transpose
    tgemm<256, false, true, true, 1><<<dim3(WIDTH / 256, MM / 128, 1), 512, SMEM256>>>(
        pzins, pzins + NW, WIDTH, pWvs, pWvs + WW, WIDTH,
        nullptr, pvs, pvs + NW, WIDTH, WIDTH, 1.f, bv, 0, 0, 1, 0, 0);
    vtrans_kernel<<<dim3(WIDTH / 32, TT / 32, BB), dim3(32, 8)>>>();

    // 6) scores + softmax -> split probs
    attn_scores_kernel<<<dim3(BB * NHEADS, TT / 128), 128>>>();

    // 7) o = P @ V^T per (b,h) -> split attno
    tgemm<256, false, false, false, 1><<<dim3(DH_V / 256, TT / 128, BB * NHEADS), 512, SMEM256>>>(
        pprs, pprs + PP, TT, pvTs, pvTs + NW, TT,
        nullptr, pats, pats + NW, WIDTH, TT, 1.f, nullptr,
        (long)TT * TT, (long)DH_V * TT, NHEADS, (long)TT * WIDTH, (long)DH_V);

    // 8) z_pred_ = relu(o @ Wo^T + bo) -> fp32 + split
    tgemm<256, true, true, false, 2><<<dim3(WIDTH / 256, MM / 128, 1), 512, SMEM256>>>(
        pats, pats + NW, WIDTH, pWos, pWos + WW, WIDTH,
        pzpred, pzps, pzps + NW, WIDTH, WIDTH, 1.f, bo, 0, 0, 1, 0, 0);

    // 9) Dz = z_pred_ @ D  (via DT), split-K 2 -> reduce
    tgemm<256, false, false, false, 0><<<dim3(DIMIN / 256, MM / 128, 2), 512, SMEM256>>>(
        pzps, pzps + NW, WIDTH, pDTs, pDTs + WD, WIDTH,
        ppart, nullptr, nullptr, DIMIN, WIDTH / 2, 1.f, nullptr,
        WIDTH / 2, WIDTH / 2, 1, ND, 0);
    reduce_kernel<false><<<(ND / 4 + 255) / 256, 256>>>(
        ppart, ND, 2, pDz, nullptr, DIMIN, ND / 4);

    // 10) proj + residual -> split x2
    proj_kernel<<<MM, 256>>>();

    // 11) z_novel = relu(lam * x2 @ D^T) -> fp32
    tgemm<256, true, false, false, 0><<<dim3(WIDTH / 256, MM / 128, 1), 512, SMEM256>>>(
        px2s, px2s + ND, DIMIN, pDs, pDs + WD, DIMIN,
        pznov, nullptr, nullptr, WIDTH, DIMIN, LAM, nullptr, 0, 0, 1, 0, 0);

    // 12) top-k + z sum -> split zsum
    topk_zsum_kernel<<<MM, 256>>>(kval);

    // 13) x_recons = zsum @ D + b (via DT), split-K 2 -> reduce + bvec -> d_out
    tgemm<256, false, false, false, 0><<<dim3(DIMIN / 256, MM / 128, 2), 512, SMEM256>>>(
        pzss, pzss + NW, WIDTH, pDTs, pDTs + WD, WIDTH,
        ppart, nullptr, nullptr, DIMIN, WIDTH / 2, 1.f, nullptr,
        WIDTH / 2, WIDTH / 2, 1, ND, 0);
    reduce_kernel<true><<<(ND / 4 + 255) / 256, 256>>>(
        ppart, ND, 2, (float*)d_out, bvec, DIMIN, ND / 4);
}

// round 9
// speedup vs baseline: 1.4716x; 1.1283x over previous
#include <cuda_runtime.h>
#include <cuda_bf16.h>
#include <math.h>

#define BB      8
#define TT      512
#define DIMIN   768
#define WIDTH   8192
#define NHEADS  8
#define NEMBDS  128
#define DH_QK   16
#define DH_V    1024
#define MM      (BB * TT)          /* 4096 */
#define LAM     (1.0f / 3072.0f)
#define EPSV    1e-6f
#define KT      64                 /* K-tile elems (128B bf16 rows) */
#define NSTAGE  3
#define STB     65536              /* bytes per stage: Ah16K Al16K Bh16K Bl16K */

// ---------------- fp32 scratch ----------------------------------------------
__device__ float g_x     [MM * DIMIN];
__device__ float g_q     [MM * NEMBDS];
__device__ float g_k     [MM * NEMBDS];
__device__ float g_Dz    [MM * DIMIN];
__device__ float g_zpred [MM * WIDTH];
__device__ float g_znov  [MM * WIDTH];
__device__ float g_proj  [MM];
__device__ float g_part  [2 * MM * DIMIN];           /* >= 8*MM*NEMBDS */

// ---------------- bf16 hi/lo split buffers ([0]=hi, [1]=lo) ------------------
__device__ __align__(256) __nv_bfloat16 s_x    [2][MM * DIMIN];
__device__ __align__(256) __nv_bfloat16 s_x2   [2][MM * DIMIN];
__device__ __align__(256) __nv_bfloat16 s_D    [2][WIDTH * DIMIN];
__device__ __align__(256) __nv_bfloat16 s_DT   [2][DIMIN * WIDTH];
__device__ __align__(256) __nv_bfloat16 s_Wk   [2][NEMBDS * WIDTH];
__device__ __align__(256) __nv_bfloat16 s_Wq   [2][NEMBDS * WIDTH];
__device__ __align__(256) __nv_bfloat16 s_Wv   [2][WIDTH * WIDTH];
__device__ __align__(256) __nv_bfloat16 s_Wo   [2][WIDTH * WIDTH];
__device__ __align__(256) __nv_bfloat16 s_zin  [2][MM * WIDTH];
__device__ __align__(256) __nv_bfloat16 s_v    [2][MM * WIDTH];
__device__ __align__(256) __nv_bfloat16 s_vT   [2][MM * WIDTH];
__device__ __align__(256) __nv_bfloat16 s_pr   [2][(long)BB * NHEADS * TT * TT];
__device__ __align__(256) __nv_bfloat16 s_at   [2][MM * WIDTH];
__device__ __align__(256) __nv_bfloat16 s_zp   [2][MM * WIDTH];
__device__ __align__(256) __nv_bfloat16 s_zs   [2][MM * WIDTH];

// ---------------- helpers ----------------------------------------------------
__device__ __forceinline__ unsigned smem_u32(const void* p) {
    unsigned a;
    asm("{ .reg .u64 t; cvta.to.shared.u64 t, %1; cvt.u32.u64 %0, t; }"
        : "=r"(a) : "l"(p));
    return a;
}
__device__ __forceinline__ unsigned swz(unsigned off) {
    return off ^ ((off >> 3) & 0x70);
}
__device__ __forceinline__ void cpa(unsigned dst, const void* src, int sz) {
    asm volatile("cp.async.cg.shared.global [%0], [%1], 16, %2;"
                 :: "r"(dst), "l"(src), "r"(sz) : "memory");
}
#define CPA_COMMIT() asm volatile("cp.async.commit_group;" ::: "memory")
#define CPA_WAIT1()  asm volatile("cp.async.wait_group 1;" ::: "memory")
#define CPA_WAIT0()  asm volatile("cp.async.wait_group 0;" ::: "memory")

#define LDSM4(r, a)                                                             \
    asm volatile("ldmatrix.sync.aligned.m8n8.x4.shared.b16 {%0,%1,%2,%3},[%4];" \
                 : "=r"((r)[0]), "=r"((r)[1]), "=r"((r)[2]), "=r"((r)[3])       \
                 : "r"(a))
#define LDSM2(r, a)                                                             \
    asm volatile("ldmatrix.sync.aligned.m8n8.x2.shared.b16 {%0,%1},[%2];"       \
                 : "=r"((r)[0]), "=r"((r)[1]) : "r"(a))
#define MMA(d, a, b)                                                            \
    asm volatile("mma.sync.aligned.m16n8k16.row.col.f32.bf16.bf16.f32 "         \
                 "{%0,%1,%2,%3},{%4,%5,%6,%7},{%8,%9},{%0,%1,%2,%3};"           \
                 : "+f"((d)[0]), "+f"((d)[1]), "+f"((d)[2]), "+f"((d)[3])       \
                 : "r"((a)[0]), "r"((a)[1]), "r"((a)[2]), "r"((a)[3]),          \
                   "r"((b)[0]), "r"((b)[1]))

__device__ __forceinline__ void split1(float v, __nv_bfloat16& h, __nv_bfloat16& l) {
    h = __float2bfloat16(v);
    l = __float2bfloat16(v - __bfloat162float(h));
}

// ---------------- GEMM: pre-split bf16 operands, cp.async 3-stage ------------
// C = act(alpha * A @ B^T + bias), A (M x K) hi/lo, B (N x K) hi/lo, row-major.
// EPI: 0 = fp32 (Cf), 1 = split (Ch/Cl), 2 = both.
// Inner loop: pass-major MMA order (hh, hl, lh) to break accumulator RAW chains.
template<bool RELU, bool BIAS, bool SHIFT, int EPI>
__global__ void __launch_bounds__(256, 1) tgemm(
    const __nv_bfloat16* __restrict__ Ah, const __nv_bfloat16* __restrict__ Al, int lda,
    const __nv_bfloat16* __restrict__ Bh, const __nv_bfloat16* __restrict__ Bl, int ldb,
    float* __restrict__ Cf, __nv_bfloat16* __restrict__ Ch, __nv_bfloat16* __restrict__ Cl,
    int ldc, int K, float alpha, const float* __restrict__ bias,
    long sA, long sB, int zdiv, long sCo, long sCi)
{
    extern __shared__ char sm[];
    const unsigned sb = smem_u32(sm);
    const int tid = threadIdx.x, wid = tid >> 5, lane = tid & 31;

    const int z = blockIdx.z;
    Ah += (long)z * sA;  Al += (long)z * sA;
    Bh += (long)z * sB;  Bl += (long)z * sB;
    const long coff = (long)(z / zdiv) * sCo + (long)(z % zdiv) * sCi;

    const int m0 = blockIdx.y * 128;
    const int n0 = blockIdx.x * 128;
    const int mw = (wid & 1) * 64;
    const int nw = (wid >> 1) * 32;

    float acc[4][4][4];
#pragma unroll
    for (int i = 0; i < 4; i++)
#pragma unroll
        for (int j = 0; j < 4; j++)
#pragma unroll
            for (int l = 0; l < 4; l++) acc[i][j][l] = 0.f;

    const int nkt = K / KT;

    // full tile coverage: 128 rows x 8 x 16B chunks = 1024 chunks per tensor
    auto issue = [&](int kt) {
        const unsigned st = sb + (kt % NSTAGE) * STB;
#pragma unroll
        for (int i = 0; i < 4; i++) {
            int idx = i * 256 + tid;            // 0..1023
            int row = idx >> 3, c = idx & 7;
            unsigned d = st + swz(row * 128 + c * 16);
            long off; int sz = 16;
            if (SHIFT) {
                int gr = m0 + row;
                int ok = (gr & (TT - 1)) != 0;
                off = (long)(ok ? gr - 1 : 0) * lda + kt * KT + c * 8;
                sz = ok ? 16 : 0;
            } else {
                off = (long)(m0 + row) * lda + kt * KT + c * 8;
            }
            cpa(d,         Ah + off, sz);
            cpa(d + 16384, Al + off, sz);
        }
#pragma unroll
        for (int i = 0; i < 4; i++) {
            int idx = i * 256 + tid;
            int row = idx >> 3, c = idx & 7;
            unsigned d = st + 32768 + swz(row * 128 + c * 16);
            long off = (long)(n0 + row) * ldb + kt * KT + c * 8;
            cpa(d,         Bh + off, 16);
            cpa(d + 16384, Bl + off, 16);
        }
        CPA_COMMIT();
    };

    issue(0);
    issue(1);

    const int arow = lane & 15, ach = lane >> 4;
    const int brow = lane & 7,  bch = (lane >> 3) & 1;

    for (int kt = 0; kt < nkt; kt++) {
        if (kt == nkt - 1) { CPA_WAIT0(); } else { CPA_WAIT1(); }
        __syncthreads();
        // single barrier per kt: stage (kt+2)%3 was fully consumed in kt-1,
        // and all warps passed that compute before this sync.
        if (kt + 2 < nkt) issue(kt + 2);

        const unsigned st  = sb + (kt % NSTAGE) * STB;
        const unsigned ahb = st, alb = st + 16384, bhb = st + 32768, blb = st + 49152;
#pragma unroll
        for (int ks = 0; ks < 4; ks++) {
            unsigned ah[4][4], al[4][4], bh[4][2], bl[4][2];
#pragma unroll
            for (int mt = 0; mt < 4; mt++) {
                unsigned o = swz((mw + mt * 16 + arow) * 128 + ks * 32 + 16 * ach);
                LDSM4(ah[mt], ahb + o);
                LDSM4(al[mt], alb + o);
            }
#pragma unroll
            for (int nt = 0; nt < 4; nt++) {
                unsigned o = swz((nw + nt * 8 + brow) * 128 + ks * 32 + 16 * bch);
                LDSM2(bh[nt], bhb + o);
                LDSM2(bl[nt], blb + o);
            }
            // pass 0: hi * hi  (16 independent accumulators)
#pragma unroll
            for (int mt = 0; mt < 4; mt++)
#pragma unroll
                for (int nt = 0; nt < 4; nt++)
                    MMA(acc[mt][nt], ah[mt], bh[nt]);
            // pass 1: hi * lo
#pragma unroll
            for (int mt = 0; mt < 4; mt++)
#pragma unroll
                for (int nt = 0; nt < 4; nt++)
                    MMA(acc[mt][nt], ah[mt], bl[nt]);
            // pass 2: lo * hi
#pragma unroll
            for (int mt = 0; mt < 4; mt++)
#pragma unroll
                for (int nt = 0; nt < 4; nt++)
                    MMA(acc[mt][nt], al[mt], bh[nt]);
        }
        // no trailing barrier: next iteration's top barrier provides it
    }

    // ---- epilogue ----
#pragma unroll
    for (int mt = 0; mt < 4; mt++) {
        int r0 = m0 + mw + mt * 16 + (lane >> 2);
#pragma unroll
        for (int nt = 0; nt < 4; nt++) {
            int c = n0 + nw + nt * 8 + (lane & 3) * 2;
            float b0 = BIAS ? bias[c] : 0.f;
            float b1 = BIAS ? bias[c + 1] : 0.f;
#pragma unroll
            for (int half = 0; half < 2; half++) {
                int r = r0 + half * 8;
                float v0 = alpha * acc[mt][nt][half * 2 + 0] + b0;
                float v1 = alpha * acc[mt][nt][half * 2 + 1] + b1;
                if (RELU) { v0 = fmaxf(v0, 0.f); v1 = fmaxf(v1, 0.f); }
                long e = coff + (long)r * ldc + c;
                if (EPI == 0 || EPI == 2)
                    *(float2*)(Cf + e) = make_float2(v0, v1);
                if (EPI == 1 || EPI == 2) {
                    __nv_bfloat162 h = __floats2bfloat162_rn(v0, v1);
                    float r0f = v0 - __bfloat162float(h.x);
                    float r1f = v1 - __bfloat162float(h.y);
                    __nv_bfloat162 l = __floats2bfloat162_rn(r0f, r1f);
                    *(__nv_bfloat162*)(Ch + e) = h;
                    *(__nv_bfloat162*)(Cl + e) = l;
                }
            }
        }
    }
}

// ---------------- split / transpose kernels ----------------------------------
__global__ void wsplit_kernel(const float* __restrict__ in,
                              __nv_bfloat16* __restrict__ hi,
                              __nv_bfloat16* __restrict__ lo, long n4) {
    long i = (long)blockIdx.x * blockDim.x + threadIdx.x;
    if (i >= n4) return;
    float4 v = ((const float4*)in)[i];
    __nv_bfloat162 h01 = __floats2bfloat162_rn(v.x, v.y);
    __nv_bfloat162 h23 = __floats2bfloat162_rn(v.z, v.w);
    __nv_bfloat162 l01 = __floats2bfloat162_rn(v.x - __bfloat162float(h01.x),
                                               v.y - __bfloat162float(h01.y));
    __nv_bfloat162 l23 = __floats2bfloat162_rn(v.z - __bfloat162float(h23.x),
                                               v.w - __bfloat162float(h23.y));
    ((uint2*)hi)[i] = make_uint2(*(unsigned*)&h01, *(unsigned*)&h23);
    ((uint2*)lo)[i] = make_uint2(*(unsigned*)&l01, *(unsigned*)&l23);
}

__global__ void prep_kernel(const float* __restrict__ xin,
                            const float* __restrict__ bvec) {
    long i = (long)blockIdx.x * blockDim.x + threadIdx.x;
    if (i >= MM * (DIMIN / 4)) return;
    int c4 = (int)(i % (DIMIN / 4));
    float4 xv = ((const float4*)xin)[i];
    float4 bv = ((const float4*)bvec)[c4];
    float4 r = make_float4(xv.x - bv.x, xv.y - bv.y, xv.z - bv.z, xv.w - bv.w);
    ((float4*)g_x)[i] = r;
    __nv_bfloat162 h01 = __floats2bfloat162_rn(r.x, r.y);
    __nv_bfloat162 h23 = __floats2bfloat162_rn(r.z, r.w);
    __nv_bfloat162 l01 = __floats2bfloat162_rn(r.x - __bfloat162float(h01.x),
                                               r.y - __bfloat162float(h01.y));
    __nv_bfloat162 l23 = __floats2bfloat162_rn(r.z - __bfloat162float(h23.x),
                                               r.w - __bfloat162float(h23.y));
    ((uint2*)&s_x[0][0])[i] = make_uint2(*(unsigned*)&h01, *(unsigned*)&h23);
    ((uint2*)&s_x[1][0])[i] = make_uint2(*(unsigned*)&l01, *(unsigned*)&l23);
}

// DT[n][k] = D[k][n], split  (D: WIDTH x DIMIN)
__global__ void dtsplit_kernel(const float* __restrict__ D) {
    __shared__ float tl[32][33];
    int n0 = blockIdx.x * 32, k0 = blockIdx.y * 32;
    int tx = threadIdx.x, ty = threadIdx.y;     // (32, 8)
#pragma unroll
    for (int j = 0; j < 4; j++)
        tl[ty + j * 8][tx] = D[(long)(k0 + ty + j * 8) * DIMIN + n0 + tx];
    __syncthreads();
#pragma unroll
    for (int j = 0; j < 4; j++) {
        int nr = ty + j * 8;
        float v = tl[tx][nr];
        __nv_bfloat16 h, l; split1(v, h, l);
        long o = (long)(n0 + nr) * WIDTH + k0 + tx;
        s_DT[0][o] = h; s_DT[1][o] = l;
    }
}

// vT[(b*8+h)*1024+d][t] = v[b*512+t][h*1024+d]
__global__ void vtrans_kernel() {
    __shared__ __nv_bfloat16 tl[2][32][33];
    int b = blockIdx.z;
    int d0 = blockIdx.x * 32;
    int t0 = blockIdx.y * 32;
    int tx = threadIdx.x, ty = threadIdx.y;   // (32, 8)
#pragma unroll
    for (int j = 0; j < 4; j++) {
        int r = ty + j * 8;
        long src = (long)(b * TT + t0 + r) * WIDTH + d0 + tx;
        tl[0][r][tx] = s_v[0][src];
        tl[1][r][tx] = s_v[1][src];
    }
    __syncthreads();
    int h = d0 >> 10, dbase = d0 & 1023;
#pragma unroll
    for (int j = 0; j < 4; j++) {
        int dr = ty + j * 8;
        long orow = (long)(b * NHEADS + h) * DH_V + dbase + dr;
        long dst = orow * TT + t0 + tx;
        s_vT[0][dst] = tl[0][tx][dr];
        s_vT[1][dst] = tl[1][tx][dr];
    }
}

// ---------------- split-K reduce ---------------------------------------------
template<bool BIAS>
__global__ void reduce_kernel(const float* __restrict__ part, long slab, int S,
                              float* __restrict__ out, const float* __restrict__ bias,
                              int N, long n4) {
    long i = (long)blockIdx.x * blockDim.x + threadIdx.x;
    if (i >= n4) return;
    float4 s = ((const float4*)part)[i];
    for (int k = 1; k < S; k++) {
        float4 p = ((const float4*)(part + (long)k * slab))[i];
        s.x += p.x; s.y += p.y; s.z += p.z; s.w += p.w;
    }
    if (BIAS) {
        int c = (int)((i * 4) % N);
        s.x += bias[c]; s.y += bias[c + 1]; s.z += bias[c + 2]; s.w += bias[c + 3];
    }
    ((float4*)out)[i] = s;
}

// ---------------- attention scores + softmax (writes split probs) ------------
__global__ void attn_scores_kernel() {
    int bh = blockIdx.x;
    int b = bh / NHEADS, h = bh % NHEADS;
    int t = blockIdx.y * 128 + threadIdx.x;

    __shared__ float kk[TT][DH_QK];
    const float* kbase = g_k + (long)b * TT * NEMBDS + h * DH_QK;
    for (int i = threadIdx.x; i < TT * (DH_QK / 4); i += 128) {
        int row = i >> 2, c4 = i & 3;
        ((float4*)&kk[row][0])[c4] =
            *(const float4*)(kbase + (long)row * NEMBDS + c4 * 4);
    }
    __syncthreads();

    float qv[DH_QK];
    const float* qb = g_q + (long)(b * TT + t) * NEMBDS + h * DH_QK;
#pragma unroll
    for (int d = 0; d < DH_QK; d++) qv[d] = qb[d];

    float srow[TT];
    float mx = -1e30f;
    for (int tp = 0; tp <= t; tp++) {
        float s = 0.f;
#pragma unroll
        for (int d = 0; d < DH_QK; d++) s += qv[d] * kk[tp][d];
        s *= 0.25f;
        mx = fmaxf(mx, s);
        srow[tp] = s;
    }
    float sum = 0.f;
    for (int tp = 0; tp <= t; tp++) sum += __expf(srow[tp] - mx);
    float inv = 1.f / sum;
    long base = ((long)bh * TT + t) * TT;
    for (int tp = 0; tp < TT; tp++) {
        float p = (tp <= t) ? __expf(srow[tp] - mx) * inv : 0.f;
        __nv_bfloat16 hh, ll; split1(p, hh, ll);
        s_pr[0][base + tp] = hh;
        s_pr[1][base + tp] = ll;
    }
}

// ---------------- projection + residual (writes split x2) --------------------
__global__ void proj_kernel() {
    int m = blockIdx.x;
    int tid = threadIdx.x;
    const float* dz = g_Dz + (long)m * DIMIN;
    const float* x  = g_x  + (long)m * DIMIN;

    float num = 0.f, den = 0.f;
    for (int j = tid; j < DIMIN; j += 256) {
        float a = dz[j], c = x[j];
        num += a * c;
        den += a * a;
    }
#pragma unroll
    for (int o = 16; o > 0; o >>= 1) {
        num += __shfl_down_sync(0xFFFFFFFFu, num, o);
        den += __shfl_down_sync(0xFFFFFFFFu, den, o);
    }
    __shared__ float sn[8], sd[8];
    __shared__ float s_projv;
    int lane = tid & 31, wd = tid >> 5;
    if (lane == 0) { sn[wd] = num; sd[wd] = den; }
    __syncthreads();
    if (tid == 0) {
        float N = 0.f, Dd = 0.f;
#pragma unroll
        for (int i = 0; i < 8; i++) { N += sn[i]; Dd += sd[i]; }
        float p = N / (Dd + EPSV);
        s_projv = p;
        g_proj[m] = p;
    }
    __syncthreads();
    float p = s_projv;
    for (int j = tid; j < DIMIN; j += 256) {
        float v = x[j] - p * dz[j];
        __nv_bfloat16 h, l; split1(v, h, l);
        long o = (long)m * DIMIN + j;
        s_x2[0][o] = h; s_x2[1][o] = l;
    }
}

// ---------------- top-k + z sum (writes split zsum) --------------------------
__global__ void topk_zsum_kernel(const int* __restrict__ kvalp) {
    int m = blockIdx.x;
    int tid = threadIdx.x;

    __shared__ unsigned sv[WIDTH];
    __shared__ int hist[256];
    __shared__ int s_target;
    __shared__ unsigned s_prefix, s_mask;

    const float* zn = g_znov + (long)m * WIDTH;
    for (int j = tid; j < WIDTH; j += 256)
        sv[j] = __float_as_uint(zn[j]);
    if (tid == 0) { s_target = *kvalp; s_prefix = 0u; s_mask = 0u; }
    __syncthreads();

    for (int byte = 3; byte >= 0; --byte) {
        hist[tid] = 0;
        __syncthreads();
        int shift = byte * 8;
        unsigned pm = s_mask, pf = s_prefix;
        for (int j = tid; j < WIDTH; j += 256) {
            unsigned v = sv[j];
            if ((v & pm) == pf) atomicAdd(&hist[(v >> shift) & 255], 1);
        }
        __syncthreads();
        if (tid == 0) {
            int cum = 0, tgt = s_target, sel = 0;
            for (int bin = 255; bin >= 0; --bin) {
                int c = hist[bin];
                if (cum + c >= tgt) { sel = bin; break; }
                cum += c;
            }
            s_target = tgt - cum;
            s_prefix = pf | ((unsigned)sel << shift);
            s_mask   = pm | (0xFFu << shift);
        }
        __syncthreads();
    }
    unsigned tau = s_prefix;
    float p = g_proj[m];
    const float* zp = g_zpred + (long)m * WIDTH;
    for (int j = tid; j < WIDTH; j += 256) {
        unsigned v = sv[j];
        float zval = (v >= tau) ? __uint_as_float(v) : 0.f;
        float o = zval + p * zp[j];
        __nv_bfloat16 h, l; split1(o, h, l);
        long e = (long)m * WIDTH + j;
        s_zs[0][e] = h; s_zs[1][e] = l;
    }
}

// ---------------- launcher ---------------------------------------------------
#define SMEMSZ (NSTAGE * STB)   /* 196608 */

extern "C" void kernel_launch(void* const* d_in, const int* in_sizes, int n_in,
                              void* d_out, int out_size)
{
    const float* x_input = (const float*)d_in[0];
    const float* D       = (const float*)d_in[1];
    const float* bvec    = (const float*)d_in[2];
    const float* Wk      = (const float*)d_in[3];
    const float* bk      = (const float*)d_in[4];
    const float* Wq      = (const float*)d_in[5];
    const float* bq      = (const float*)d_in[6];
    const float* Wv      = (const float*)d_in[7];
    const float* bv      = (const float*)d_in[8];
    const float* Wo      = (const float*)d_in[9];
    const float* bo      = (const float*)d_in[10];
    const int*   kval    = (const int*)d_in[11];

    float *pq, *pk, *pDz, *pzpred, *pznov, *ppart;
    cudaGetSymbolAddress((void**)&pq,     g_q);
    cudaGetSymbolAddress((void**)&pk,     g_k);
    cudaGetSymbolAddress((void**)&pDz,    g_Dz);
    cudaGetSymbolAddress((void**)&pzpred, g_zpred);
    cudaGetSymbolAddress((void**)&pznov,  g_znov);
    cudaGetSymbolAddress((void**)&ppart,  g_part);

    __nv_bfloat16 *pxs, *px2s, *pDs, *pDTs, *pWks, *pWqs, *pWvs, *pWos,
                  *pzins, *pvs, *pvTs, *pprs, *pats, *pzps, *pzss;
    cudaGetSymbolAddress((void**)&pxs,   s_x);
    cudaGetSymbolAddress((void**)&px2s,  s_x2);
    cudaGetSymbolAddress((void**)&pDs,   s_D);
    cudaGetSymbolAddress((void**)&pDTs,  s_DT);
    cudaGetSymbolAddress((void**)&pWks,  s_Wk);
    cudaGetSymbolAddress((void**)&pWqs,  s_Wq);
    cudaGetSymbolAddress((void**)&pWvs,  s_Wv);
    cudaGetSymbolAddress((void**)&pWos,  s_Wo);
    cudaGetSymbolAddress((void**)&pzins, s_zin);
    cudaGetSymbolAddress((void**)&pvs,   s_v);
    cudaGetSymbolAddress((void**)&pvTs,  s_vT);
    cudaGetSymbolAddress((void**)&pprs,  s_pr);
    cudaGetSymbolAddress((void**)&pats,  s_at);
    cudaGetSymbolAddress((void**)&pzps,  s_zp);
    cudaGetSymbolAddress((void**)&pzss,  s_zs);

    cudaFuncSetAttribute(tgemm<true,  false, false, 1>, cudaFuncAttributeMaxDynamicSharedMemorySize, SMEMSZ);
    cudaFuncSetAttribute(tgemm<false, false, true,  0>, cudaFuncAttributeMaxDynamicSharedMemorySize, SMEMSZ);
    cudaFuncSetAttribute(tgemm<false, false, false, 0>, cudaFuncAttributeMaxDynamicSharedMemorySize, SMEMSZ);
    cudaFuncSetAttribute(tgemm<false, true,  true,  1>, cudaFuncAttributeMaxDynamicSharedMemorySize, SMEMSZ);
    cudaFuncSetAttribute(tgemm<false, false, false, 1>, cudaFuncAttributeMaxDynamicSharedMemorySize, SMEMSZ);
    cudaFuncSetAttribute(tgemm<true,  true,  false, 2>, cudaFuncAttributeMaxDynamicSharedMemorySize, SMEMSZ);
    cudaFuncSetAttribute(tgemm<true,  false, false, 0>, cudaFuncAttributeMaxDynamicSharedMemorySize, SMEMSZ);

    // ---- input prep + weight splits ----
    prep_kernel<<<(MM * (DIMIN / 4) + 255) / 256, 256>>>(x_input, bvec);
    wsplit_kernel<<<((long)WIDTH * DIMIN / 4 + 255) / 256, 256>>>(D,  pDs,  pDs  + (long)WIDTH * DIMIN,  (long)WIDTH * DIMIN / 4);
    wsplit_kernel<<<((long)NEMBDS * WIDTH / 4 + 255) / 256, 256>>>(Wk, pWks, pWks + (long)NEMBDS * WIDTH, (long)NEMBDS * WIDTH / 4);
    wsplit_kernel<<<((long)NEMBDS * WIDTH / 4 + 255) / 256, 256>>>(Wq, pWqs, pWqs + (long)NEMBDS * WIDTH, (long)NEMBDS * WIDTH / 4);
    wsplit_kernel<<<((long)WIDTH * WIDTH / 4 + 255) / 256, 256>>>(Wv, pWvs, pWvs + (long)WIDTH * WIDTH, (long)WIDTH * WIDTH / 4);
    wsplit_kernel<<<((long)WIDTH * WIDTH / 4 + 255) / 256, 256>>>(Wo, pWos, pWos + (long)WIDTH * WIDTH, (long)WIDTH * WIDTH / 4);
    dtsplit_kernel<<<dim3(DIMIN / 32, WIDTH / 32), dim3(32, 8)>>>(D);

    const long NW = (long)MM * WIDTH;
    const long ND = (long)MM * DIMIN;
    const long NE = (long)NEMBDS * WIDTH;
    const long WW = (long)WIDTH * WIDTH;
    const long WD = (long)WIDTH * DIMIN;
    const long PP = (long)BB * NHEADS * TT * TT;

    // 2) z_in = relu(lam * x @ D^T)  -> split
    tgemm<true, false, false, 1><<<dim3(WIDTH / 128, MM / 128, 1), 256, SMEMSZ>>>(
        pxs, pxs + ND, DIMIN, pDs, pDs + WD, DIMIN,
        nullptr, pzins, pzins + NW, WIDTH, DIMIN, LAM, nullptr, 0, 0, 1, 0, 0);

    // 3) k partials (shifted A), split-K 8 -> reduce + bk
    tgemm<false, false, true, 0><<<dim3(1, MM / 128, 8), 256, SMEMSZ>>>(
        pzins, pzins + NW, WIDTH, pWks, pWks + NE, WIDTH,
        ppart, nullptr, nullptr, NEMBDS, WIDTH / 8, 1.f, nullptr,
        WIDTH / 8, WIDTH / 8, 1, (long)MM * NEMBDS, 0);
    reduce_kernel<true><<<((long)MM * NEMBDS / 4 + 255) / 256, 256>>>(
        ppart, (long)MM * NEMBDS, 8, pk, bk, NEMBDS, (long)MM * NEMBDS / 4);

    // 4) q partials, split-K 8 -> reduce + bq
    tgemm<false, false, false, 0><<<dim3(1, MM / 128, 8), 256, SMEMSZ>>>(
        pzins, pzins + NW, WIDTH, pWqs, pWqs + NE, WIDTH,
        ppart, nullptr, nullptr, NEMBDS, WIDTH / 8, 1.f, nullptr,
        WIDTH / 8, WIDTH / 8, 1, (long)MM * NEMBDS, 0);
    reduce_kernel<true><<<((long)MM * NEMBDS / 4 + 255) / 256, 256>>>(
        ppart, (long)MM * NEMBDS, 8, pq, bq, NEMBDS, (long)MM * NEMBDS / 4);

    // 5) v = shift(z_in) @ Wv^T + bv  -> split, then transpose
    tgemm<false, true, true, 1><<<dim3(WIDTH / 128, MM / 128, 1), 256, SMEMSZ>>>(
        pzins, pzins + NW, WIDTH, pWvs, pWvs + WW, WIDTH,
        nullptr, pvs, pvs + NW, WIDTH, WIDTH, 1.f, bv, 0, 0, 1, 0, 0);
    vtrans_kernel<<<dim3(WIDTH / 32, TT / 32, BB), dim3(32, 8)>>>();

    // 6) scores + softmax -> split probs
    attn_scores_kernel<<<dim3(BB * NHEADS, TT / 128), 128>>>();

    // 7) o = P @ V^T per (b,h) -> split attno
    tgemm<false, false, false, 1><<<dim3(DH_V / 128, TT / 128, BB * NHEADS), 256, SMEMSZ>>>(
        pprs, pprs + PP, TT, pvTs, pvTs + NW, TT,
        nullptr, pats, pats + NW, WIDTH, TT, 1.f, nullptr,
        (long)TT * TT, (long)DH_V * TT, NHEADS, (long)TT * WIDTH, (long)DH_V);

    // 8) z_pred_ = relu(o @ Wo^T + bo) -> fp32 + split
    tgemm<true, true, false, 2><<<dim3(WIDTH / 128, MM / 128, 1), 256, SMEMSZ>>>(
        pats, pats + NW, WIDTH, pWos, pWos + WW, WIDTH,
        pzpred, pzps, pzps + NW, WIDTH, WIDTH, 1.f, bo, 0, 0, 1, 0, 0);

    // 9) Dz = z_pred_ @ D  (via DT), split-K 2 -> reduce
    tgemm<false, false, false, 0><<<dim3(DIMIN / 128, MM / 128, 2), 256, SMEMSZ>>>(
        pzps, pzps + NW, WIDTH, pDTs, pDTs + WD, WIDTH,
        ppart, nullptr, nullptr, DIMIN, WIDTH / 2, 1.f, nullptr,
        WIDTH / 2, WIDTH / 2, 1, ND, 0);
    reduce_kernel<false><<<(ND / 4 + 255) / 256, 256>>>(
        ppart, ND, 2, pDz, nullptr, DIMIN, ND / 4);

    // 10) proj + residual -> split x2
    proj_kernel<<<MM, 256>>>();

    // 11) z_novel = relu(lam * x2 @ D^T) -> fp32
    tgemm<true, false, false, 0><<<dim3(WIDTH / 128, MM / 128, 1), 256, SMEMSZ>>>(
        px2s, px2s + ND, DIMIN, pDs, pDs + WD, DIMIN,
        pznov, nullptr, nullptr, WIDTH, DIMIN, LAM, nullptr, 0, 0, 1, 0, 0);

    // 12) top-k + z sum -> split zsum
    topk_zsum_kernel<<<MM, 256>>>(kval);

    // 13) x_recons = zsum @ D + b (via DT), split-K 2 -> reduce + bvec -> d_out
    tgemm<false, false, false, 0><<<dim3(DIMIN / 128, MM / 128, 2), 256, SMEMSZ>>>(
        pzss, pzss + NW, WIDTH, pDTs, pDTs + WD, WIDTH,
        ppart, nullptr, nullptr, DIMIN, WIDTH / 2, 1.f, nullptr,
        WIDTH / 2, WIDTH / 2, 1, ND, 0);
    reduce_kernel<true><<<(ND / 4 + 255) / 256, 256>>>(
        ppart, ND, 2, (float*)d_out, bvec, DIMIN, ND / 4);
}